// round 14
// baseline (speedup 1.0000x reference)
#include <cuda_runtime.h>
#include <math.h>

#define BB 8
#define CC 16
#define MM 32
#define KK 64
#define HH 384
#define WW 384
#define WF 193

// ---------------- scratch ----------------
__device__ float2 g_Xr[(size_t)BB*CC*WF*HH];   // [b,c,w,h]
__device__ float2 g_Yf[(size_t)BB*KK*WF*HH];   // [b,k,w,h]
__device__ float2 g_tw[384];
__device__ float2 g_part[512];
__device__ float2 g_stats[8];

__device__ __forceinline__ float2 cmulf(float2 a, float2 b) {
    return make_float2(a.x*b.x - a.y*b.y, a.x*b.y + a.y*b.x);
}
__device__ __forceinline__ void cfma(float2& acc, float2 a, float2 b) {
    acc.x += a.x*b.x; acc.x -= a.y*b.y;
    acc.y += a.x*b.y; acc.y += a.y*b.x;
}

// ---------------- small DFTs ----------------
template<int SIGN>
__device__ __forceinline__ void dft6(float2 v[6]) {
    const float S3 = 0.8660254037844386f * (float)SIGN;
    const float ct[6] = {1.f, 0.5f, -0.5f, -1.f, -0.5f, 0.5f};
    const float st[6] = {0.f, S3, S3, 0.f, -S3, -S3};
    float2 o[6];
#pragma unroll
    for (int r = 0; r < 6; r++) {
        float re = v[0].x, im = v[0].y;
#pragma unroll
        for (int j = 1; j < 6; j++) {
            const int k = (j*r) % 6;
            re += v[j].x*ct[k] - v[j].y*st[k];
            im += v[j].x*st[k] + v[j].y*ct[k];
        }
        o[r] = make_float2(re, im);
    }
#pragma unroll
    for (int r = 0; r < 6; r++) v[r] = o[r];
}

template<int SIGN>
__device__ __forceinline__ void dft8(float2 v[8]) {
    const float R2 = 0.70710678118654752f;
    const float S = (float)SIGN;
    const float ct[8] = {1.f, R2, 0.f, -R2, -1.f, -R2, 0.f, R2};
    const float st[8] = {0.f, R2*S, 1.f*S, R2*S, 0.f, -R2*S, -1.f*S, -R2*S};
    float2 o[8];
#pragma unroll
    for (int r = 0; r < 8; r++) {
        float re = v[0].x, im = v[0].y;
#pragma unroll
        for (int j = 1; j < 8; j++) {
            const int k = (j*r) & 7;
            re += v[j].x*ct[k] - v[j].y*st[k];
            im += v[j].x*st[k] + v[j].y*ct[k];
        }
        o[r] = make_float2(re, im);
    }
#pragma unroll
    for (int r = 0; r < 8; r++) v[r] = o[r];
}

#define LSTR 390

// reg-in / reg-out FFT (caller synced; pa/pb per-line regions)
template<int SIGN>
__device__ __forceinline__ void fft384_rr(float2 vin[6], float2 vout[8],
                                          float2* pa, float2* pb,
                                          const float2* tw, int t) {
    dft6<SIGN>(vin);
#pragma unroll
    for (int r = 0; r < 6; r++) {
        float2 w = tw[t*r];
        if (SIGN > 0) w.y = -w.y;
        pb[6*t + r] = cmulf(vin[r], w);
    }
    __syncthreads();
    if (t < 48) {
        const int q = t % 6, p = t / 6;
        float2 v[8];
#pragma unroll
        for (int j = 0; j < 8; j++) v[j] = pb[q + 6*(p + 8*j)];
        dft8<SIGN>(v);
#pragma unroll
        for (int r = 0; r < 8; r++) {
            float2 w = tw[6*p*r];
            if (SIGN > 0) w.y = -w.y;
            pa[q + 6*(8*p + r)] = cmulf(v[r], w);
        }
    }
    __syncthreads();
    if (t < 48) {
#pragma unroll
        for (int j = 0; j < 8; j++) vout[j] = pa[t + 48*j];
        dft8<SIGN>(vout);
    }
}

// ---------------- twiddle init ----------------
__global__ void k_tw() {
    int i = threadIdx.x;
    if (i < 384) {
        float s, c;
        sincosf(-6.28318530717958647692f * (float)i / 384.f, &s, &c);
        g_tw[i] = make_float2(c, s);
    }
}

// ---------------- stats ----------------
__global__ void k_stats1(const float* __restrict__ x) {
    const int b = blockIdx.x >> 6, sl = blockIdx.x & 63;
    const float4* p = (const float4*)x + (size_t)b*589824 + (size_t)sl*9216;
    float s = 0.f, q = 0.f;
    for (int i = threadIdx.x; i < 9216; i += 256) {
        float4 v = p[i];
        s += v.x + v.y + v.z + v.w;
        q += v.x*v.x + v.y*v.y + v.z*v.z + v.w*v.w;
    }
    __shared__ float rs[256], rq[256];
    rs[threadIdx.x] = s; rq[threadIdx.x] = q;
    __syncthreads();
    for (int o = 128; o > 0; o >>= 1) {
        if (threadIdx.x < o) { rs[threadIdx.x] += rs[threadIdx.x+o]; rq[threadIdx.x] += rq[threadIdx.x+o]; }
        __syncthreads();
    }
    if (threadIdx.x == 0) g_part[blockIdx.x] = make_float2(rs[0], rq[0]);
}

__global__ void k_stats2() {
    __shared__ float2 sp[512];
    sp[threadIdx.x] = g_part[threadIdx.x];
    __syncthreads();
    if (threadIdx.x < 8) {
        float s = 0.f, q = 0.f;
        for (int i = 0; i < 64; i++) { float2 v = sp[threadIdx.x*64 + i]; s += v.x; q += v.y; }
        const float Nb = (float)(CC*HH*WW);
        float mean = s / Nb;
        float var = q / Nb - mean*mean;
        g_stats[threadIdx.x] = make_float2(mean, rsqrtf(var + 1e-5f));
    }
}

// ---------------- forward rows: 8 lines/block, 512 threads, coalesced I/O -------
// Input: 8 contiguous x rows staged through smem (128B loads).
// Output: stage-3 result kept in pb; stores n-major/h-minor (64B transactions).
__global__ void __launch_bounds__(512) k_fwd_u(const float* __restrict__ x) {
    __shared__ float2 sa[8*LSTR], sb[8*LSTR], tw[384];
    float* saf = (float*)sa;                   // staging: row*780 + n
    const int tid = threadIdx.x;
    for (int i = tid; i < 384; i += 512) tw[i] = g_tw[i];
    const int l = tid & 7, t = tid >> 3;
    const int line0 = blockIdx.x * 8;          // 8 consecutive h of one (b,c)
    const int h0 = line0 % 384;
    const int c = (line0 / 384) & 15;
    const int b = line0 / (384*16);
    const float* xr = x + (((size_t)(b*CC + c)*HH + h0) * WW);   // 3072 contiguous floats

    // fully-coalesced input staging
    for (int i = tid; i < 8*384; i += 512) {
        saf[(i / 384)*780 + (i % 384)] = xr[i];
    }
    __syncthreads();

    float2 vin[6];
#pragma unroll
    for (int j = 0; j < 6; j++) vin[j] = make_float2(saf[l*780 + t + 64*j], 0.f);

    float2* pa = sa + l*LSTR;
    float2* pb = sb + l*LSTR;
    // stage 1 (regs -> pb); all saf reads above complete before stage-2 writes sa
    dft6<-1>(vin);
#pragma unroll
    for (int r = 0; r < 6; r++) pb[6*t + r] = cmulf(vin[r], tw[t*r]);
    __syncthreads();
    // stage 2 (pb -> pa)
    if (t < 48) {
        const int q = t % 6, p = t / 6;
        float2 v[8];
#pragma unroll
        for (int j = 0; j < 8; j++) v[j] = pb[q + 6*(p + 8*j)];
        dft8<-1>(v);
#pragma unroll
        for (int r = 0; r < 8; r++) pa[q + 6*(8*p + r)] = cmulf(v[r], tw[6*p*r]);
    }
    __syncthreads();
    // stage 3 (pa -> pb, result in smem)
    if (t < 48) {
        float2 v[8];
#pragma unroll
        for (int j = 0; j < 8; j++) v[j] = pa[t + 48*j];
        dft8<-1>(v);
#pragma unroll
        for (int r = 0; r < 8; r++) pb[t + 48*r] = v[r];
    }
    __syncthreads();

    // coalesced transposed store: warp = 4 bins x 8 consecutive h (64B)
    float2* dst = g_Xr + ((size_t)(b*CC + c)*WF)*HH + h0;
    for (int i = tid; i < WF*8; i += 512) {
        const int n = i >> 3, lh = i & 7;
        dst[(size_t)n*HH + lh] = sb[lh*LSTR + n];
    }
}

// ---------------- forward column FFTs on g_Xr ------------------------------------
__global__ void k_colf() {
    __shared__ float2 sa[4*LSTR], sb[4*LSTR], tw[384];
    for (int i = threadIdx.x; i < 384; i += 256) tw[i] = g_tw[i];
    const int l = threadIdx.x & 3, t = threadIdx.x >> 2;
    const size_t line = (size_t)blockIdx.x*4 + l;
    float2* g = g_Xr + line*HH;
    float2 vin[6], vout[8];
#pragma unroll
    for (int j = 0; j < 6; j++) vin[j] = g[t + 64*j];
    __syncthreads();
    fft384_rr<-1>(vin, vout, sa + l*LSTR, sb + l*LSTR, tw, t);
    if (t < 48) {
#pragma unroll
        for (int r = 0; r < 8; r++) g[t + 48*r] = vout[r];
    }
}

// ---------------- FUSED: (B@Xf)*T -> column IFFT -> C-GEMM -> Yf (round-8) -------
#define FZ_ZM    0                      // sZm: [32][386] float2 = 98816
#define FZ_UNI   98816                  // union: sX [16][384] f2 / pp 16 x 390 f2
#define FZ_CT    148736                 // sCt: [32][64] float2 = 16384
#define FZ_BT    165120                 // sBt: [16][32] float2 = 4096
#define FZ_TW    169216                 // tw: 384 float2 = 3072
#define FZ_PAR   172288                 // sPar: [32][8] float = 1024
#define FZ_TOTAL 173312

__global__ void __launch_bounds__(512, 1) k_fused(
    const float* __restrict__ B_re, const float* __restrict__ B_im,
    const float* __restrict__ C_re, const float* __restrict__ C_im,
    const float* __restrict__ theta, const float* __restrict__ alpha_raw,
    const float* __restrict__ beta,  const float* __restrict__ log_dc,
    const float* __restrict__ log_tau, const float* __restrict__ log_scale,
    const float* __restrict__ log_bw) {
    extern __shared__ char dynsm[];
    float2* sZm  = (float2*)(dynsm + FZ_ZM);
    float2* sX   = (float2*)(dynsm + FZ_UNI);
    float2* pp   = (float2*)(dynsm + FZ_UNI);
    float2* sCt  = (float2*)(dynsm + FZ_CT);
    float2* sBt  = (float2*)(dynsm + FZ_BT);
    float2* tw   = (float2*)(dynsm + FZ_TW);
    float*  sPar = (float*)(dynsm + FZ_PAR);

    const int tid = threadIdx.x;
    const int b = blockIdx.x / WF;
    const int w = blockIdx.x % WF;

    for (int i = tid; i < 384; i += 512) tw[i] = g_tw[i];
    for (int i = tid; i < CC*MM; i += 512) {
        const int c = i >> 5, m = i & 31;
        sBt[i] = make_float2(B_re[m*CC + c], B_im[m*CC + c]);
    }
    for (int i = tid; i < MM*KK; i += 512) {
        const int m = i >> 6, k = i & 63;
        sCt[i] = make_float2(C_re[k*MM + m], C_im[k*MM + m]);
    }
    if (tid < MM) {
        const int m = tid;
        float ar = alpha_raw[m];
        float spa = (ar > 20.f) ? ar : log1pf(expf(ar));
        float wc = expf(log_bw[m]);
        sPar[m*8+0] = spa;
        sPar[m*8+1] = beta[m];
        sPar[m*8+2] = expf(log_scale[m]);
        sPar[m*8+3] = expf(log_tau[m]);
        sPar[m*8+4] = expf(log_dc[m]);
        sPar[m*8+5] = 1.f / (wc*wc);
        sPar[m*8+6] = cosf(theta[m]);
        sPar[m*8+7] = sinf(theta[m]);
    }
    __syncthreads();

    // ---- T in registers ----
    const float TPN = 6.28318530717958647692f / 384.f;
    const float ox = (float)w * TPN;
    float2 Treg[24];
#pragma unroll
    for (int it = 0; it < 3; it++) {
        const int item = tid + 512*it;
        const int mq = item / 192, hp = item % 192;
#pragma unroll
        for (int mm = 0; mm < 4; mm++) {
            const int m = mq*4 + mm;
#pragma unroll
            for (int hh = 0; hh < 2; hh++) {
                const int h = 2*hp + hh;
                const float oy = (float)((h < 192) ? h : h - 384) * TPN;
                const float vd = sPar[m*8+6]*ox + sPar[m*8+7]*oy;
                const float w2 = ox*ox + oy*oy;
                const float wp2 = w2 - vd*vd;
                float Dre = sPar[m*8+0] + sPar[m*8+3]*wp2;
                float Dim = sPar[m*8+2]*vd - sPar[m*8+1];
                const float qq = w2 * sPar[m*8+5];
                const float q2 = qq*qq;
                const float bt = 1.f + q2*q2;
                Dre *= bt; Dim *= bt;
                const float inv = sPar[m*8+4] / (Dre*Dre + Dim*Dim);
                Treg[it*8 + mm*2 + hh] = make_float2(Dre*inv, -Dim*inv);
            }
        }
    }

    const float HWf = (float)(HH*WW);
    const float2 st = g_stats[b];
    const float mean = st.x, rstd = st.y;

    // ---- load Xf tile (normalized); DC fix for all channels ----
    {
        const float4* src = (const float4*)(g_Xr + ((size_t)(b*CC)*WF + w)*HH);
#pragma unroll
        for (int itr = 0; itr < 6; itr++) {
            const int idx = tid + 512*itr;
            const int c = idx / 192, q = idx % 192;
            float4 v = *(const float4*)((const char*)src + ((size_t)c*WF*HH + 2*q)*8);
            if (w == 0 && q == 0) v.x -= mean * HWf;
            v.x *= rstd; v.y *= rstd; v.z *= rstd; v.w *= rstd;
            *(float4*)(sX + c*384 + 2*q) = v;
        }
    }
    __syncthreads();

    // ---- GEMM1 + T: Zspec[m][h] ----
#pragma unroll
    for (int it = 0; it < 3; it++) {
        const int item = tid + 512*it;
        const int mq = item / 192, hp = item % 192;
        float2 acc[4][2];
#pragma unroll
        for (int mm = 0; mm < 4; mm++) { acc[mm][0] = make_float2(0.f,0.f); acc[mm][1] = make_float2(0.f,0.f); }
#pragma unroll
        for (int c = 0; c < CC; c++) {
            const float4 xv = *(const float4*)(sX + c*384 + 2*hp);
            const float2 x0 = make_float2(xv.x, xv.y);
            const float2 x1 = make_float2(xv.z, xv.w);
            const float4 ba = *(const float4*)(sBt + c*32 + mq*4);
            const float4 bb = *(const float4*)(sBt + c*32 + mq*4 + 2);
            const float2 b0 = make_float2(ba.x, ba.y);
            const float2 b1 = make_float2(ba.z, ba.w);
            const float2 b2 = make_float2(bb.x, bb.y);
            const float2 b3 = make_float2(bb.z, bb.w);
            cfma(acc[0][0], b0, x0); cfma(acc[0][1], b0, x1);
            cfma(acc[1][0], b1, x0); cfma(acc[1][1], b1, x1);
            cfma(acc[2][0], b2, x0); cfma(acc[2][1], b2, x1);
            cfma(acc[3][0], b3, x0); cfma(acc[3][1], b3, x1);
        }
#pragma unroll
        for (int mm = 0; mm < 4; mm++) {
            const float2 z0 = cmulf(acc[mm][0], Treg[it*8 + mm*2 + 0]);
            const float2 z1 = cmulf(acc[mm][1], Treg[it*8 + mm*2 + 1]);
            *(float4*)(sZm + (mq*4 + mm)*386 + 2*hp) = make_float4(z0.x, z0.y, z1.x, z1.y);
        }
    }
    __syncthreads();

    // ---- column IFFT of 32 rows (4 groups of 8 lines) ----
    {
        const int l = tid & 7, t = tid >> 3;
        float2* pa = pp + l*LSTR;
        float2* pb = pp + 8*LSTR + l*LSTR;
#pragma unroll 1
        for (int g = 0; g < 4; g++) {
            float2* zrow = sZm + (g*8 + l)*386;
            float2 vin[6], vout[8];
#pragma unroll
            for (int j = 0; j < 6; j++) vin[j] = zrow[t + 64*j];
            fft384_rr<1>(vin, vout, pa, pb, tw, t);
            if (t < 48) {
#pragma unroll
                for (int r = 0; r < 8; r++) zrow[t + 48*r] = vout[r];
            }
            __syncthreads();
        }
    }

    // ---- GEMM2 (4k x 2h): Yf[k][h] = sum_m C[k][m] * Z[m][h] ----
#pragma unroll 1
    for (int it = 0; it < 6; it++) {
        const int item = tid + 512*it;
        const int kq = item / 192, hp = item % 192;
        float2 a00 = make_float2(0.f,0.f), a01 = a00, a10 = a00, a11 = a00;
        float2 a20 = a00, a21 = a00, a30 = a00, a31 = a00;
#pragma unroll
        for (int m = 0; m < MM; m++) {
            const float4 zz = *(const float4*)(sZm + m*386 + 2*hp);
            const float2 z0 = make_float2(zz.x, zz.y);
            const float2 z1 = make_float2(zz.z, zz.w);
            const float4 ca = *(const float4*)(sCt + m*64 + kq*4);
            const float4 cb = *(const float4*)(sCt + m*64 + kq*4 + 2);
            const float2 c0 = make_float2(ca.x, ca.y);
            const float2 c1 = make_float2(ca.z, ca.w);
            const float2 c2 = make_float2(cb.x, cb.y);
            const float2 c3 = make_float2(cb.z, cb.w);
            cfma(a00, c0, z0); cfma(a01, c0, z1);
            cfma(a10, c1, z0); cfma(a11, c1, z1);
            cfma(a20, c2, z0); cfma(a21, c2, z1);
            cfma(a30, c3, z0); cfma(a31, c3, z1);
        }
        const size_t base = ((size_t)(b*KK + kq*4)*WF + w)*HH + 2*hp;
        *(float4*)(g_Yf + base)                    = make_float4(a00.x, a00.y, a01.x, a01.y);
        *(float4*)(g_Yf + base + (size_t)WF*HH)    = make_float4(a10.x, a10.y, a11.x, a11.y);
        *(float4*)(g_Yf + base + (size_t)2*WF*HH)  = make_float4(a20.x, a20.y, a21.x, a21.y);
        *(float4*)(g_Yf + base + (size_t)3*WF*HH)  = make_float4(a30.x, a30.y, a31.x, a31.y);
    }
}

// ---------------- inverse rows: 8 lines/block, 512 threads, coalesced I/O -------
__global__ void __launch_bounds__(512) k_inv_p(float* __restrict__ y) {
    __shared__ float2 sa[8*LSTR], sb[8*LSTR], tw[384];
    const int tid = threadIdx.x;
    for (int i = tid; i < 384; i += 512) tw[i] = g_tw[i];
    const int l = tid & 7, t = tid >> 3;
    const int line0 = blockIdx.x * 8;
    const int h0 = line0 % 384;
    const int kp = (line0 / 384) & 31;
    const int b  = line0 / (384*32);
    const int h = h0 + l;
    const size_t base1 = ((size_t)(b*KK + 2*kp)*WF)*HH + h;
    const size_t base2 = base1 + (size_t)WF*HH;

    float2 vin[6];
#pragma unroll
    for (int i = 0; i < 6; i++) {
        const int w = t + 64*i;
        const int wi = (w < WF) ? w : (384 - w);
        const float2 q1 = g_Yf[base1 + (size_t)wi*HH];
        const float2 q2 = g_Yf[base2 + (size_t)wi*HH];
        float2 z;
        if (w == 0 || w == 192) {
            z = make_float2(q1.x, q2.x);
        } else if (w < WF) {
            z = make_float2(q1.x - q2.y, q1.y + q2.x);
        } else {
            z = make_float2(q1.x + q2.y, q2.x - q1.y);
        }
        vin[i] = z;
    }
    __syncthreads();     // tw staged

    float2* pa = sa + l*LSTR;
    float2* pb = sb + l*LSTR;
    dft6<1>(vin);
#pragma unroll
    for (int r = 0; r < 6; r++) {
        float2 wv = tw[t*r]; wv.y = -wv.y;
        pb[6*t + r] = cmulf(vin[r], wv);
    }
    __syncthreads();
    if (t < 48) {
        const int q = t % 6, p = t / 6;
        float2 v[8];
#pragma unroll
        for (int j = 0; j < 8; j++) v[j] = pb[q + 6*(p + 8*j)];
        dft8<1>(v);
#pragma unroll
        for (int r = 0; r < 8; r++) {
            float2 wv = tw[6*p*r]; wv.y = -wv.y;
            pa[q + 6*(8*p + r)] = cmulf(v[r], wv);
        }
    }
    __syncthreads();
    if (t < 48) {
        float2 v[8];
#pragma unroll
        for (int j = 0; j < 8; j++) v[j] = pa[t + 48*j];
        dft8<1>(v);
#pragma unroll
        for (int r = 0; r < 8; r++) pb[t + 48*r] = v[r];
    }
    __syncthreads();

    const float sc = 1.f / (float)(HH*WW);
    float* y0 = y + ((size_t)(b*KK + 2*kp)*HH + h0) * WW;
    float* y1 = y0 + (size_t)HH*WW;
#pragma unroll
    for (int i = 0; i < 6; i++) {
        const int idx = tid + 512*i;
        const int rh = idx / 384;
        const int n  = idx % 384;
        const float2 v = sb[rh*LSTR + n];
        y0[(size_t)rh*WW + n] = v.x * sc;
        y1[(size_t)rh*WW + n] = v.y * sc;
    }
}

// ---------------- launch ----------------
extern "C" void kernel_launch(void* const* d_in, const int* in_sizes, int n_in,
                              void* d_out, int out_size) {
    const float* x         = (const float*)d_in[0];
    const float* theta     = (const float*)d_in[1];
    const float* B_re      = (const float*)d_in[2];
    const float* B_im      = (const float*)d_in[3];
    const float* C_re      = (const float*)d_in[4];
    const float* C_im      = (const float*)d_in[5];
    const float* alpha_raw = (const float*)d_in[6];
    const float* beta      = (const float*)d_in[7];
    const float* log_dc    = (const float*)d_in[8];
    const float* log_tau   = (const float*)d_in[9];
    const float* log_scale = (const float*)d_in[10];
    const float* log_bw    = (const float*)d_in[11];
    float* y = (float*)d_out;

    cudaFuncSetAttribute(k_fused, cudaFuncAttributeMaxDynamicSharedMemorySize, FZ_TOTAL);

    k_tw<<<1, 384>>>();
    k_stats1<<<512, 256>>>(x);
    k_stats2<<<1, 512>>>();
    k_fwd_u<<<(BB*CC*HH)/8, 512>>>(x);                  // 6144 blocks
    k_colf<<<(BB*CC*WF)/4, 256>>>();                    // 6176 blocks
    k_fused<<<BB*WF, 512, FZ_TOTAL>>>(B_re, B_im, C_re, C_im, theta, alpha_raw,
                                      beta, log_dc, log_tau, log_scale, log_bw);
    k_inv_p<<<(BB*MM*HH)/8, 512>>>(y);                  // 12288 blocks
}

// round 15
// speedup vs baseline: 1.0300x; 1.0300x over previous
#include <cuda_runtime.h>
#include <math.h>

#define BB 8
#define CC 16
#define MM 32
#define KK 64
#define HH 384
#define WW 384
#define WF 193

// ---------------- scratch ----------------
__device__ float2 g_Xr[(size_t)BB*CC*WF*HH];   // [b,c,w,h]
__device__ float2 g_Yf[(size_t)BB*KK*WF*HH];   // [b,k,w,h]
__device__ float2 g_tw[384];
__device__ float2 g_part[512];
__device__ float2 g_stats[8];

__device__ __forceinline__ float2 cmulf(float2 a, float2 b) {
    return make_float2(a.x*b.x - a.y*b.y, a.x*b.y + a.y*b.x);
}
__device__ __forceinline__ void cfma(float2& acc, float2 a, float2 b) {
    acc.x += a.x*b.x; acc.x -= a.y*b.y;
    acc.y += a.x*b.y; acc.y += a.y*b.x;
}

// ---------------- small DFTs ----------------
template<int SIGN>
__device__ __forceinline__ void dft6(float2 v[6]) {
    const float S3 = 0.8660254037844386f * (float)SIGN;
    const float ct[6] = {1.f, 0.5f, -0.5f, -1.f, -0.5f, 0.5f};
    const float st[6] = {0.f, S3, S3, 0.f, -S3, -S3};
    float2 o[6];
#pragma unroll
    for (int r = 0; r < 6; r++) {
        float re = v[0].x, im = v[0].y;
#pragma unroll
        for (int j = 1; j < 6; j++) {
            const int k = (j*r) % 6;
            re += v[j].x*ct[k] - v[j].y*st[k];
            im += v[j].x*st[k] + v[j].y*ct[k];
        }
        o[r] = make_float2(re, im);
    }
#pragma unroll
    for (int r = 0; r < 6; r++) v[r] = o[r];
}

template<int SIGN>
__device__ __forceinline__ void dft8(float2 v[8]) {
    const float R2 = 0.70710678118654752f;
    const float S = (float)SIGN;
    const float ct[8] = {1.f, R2, 0.f, -R2, -1.f, -R2, 0.f, R2};
    const float st[8] = {0.f, R2*S, 1.f*S, R2*S, 0.f, -R2*S, -1.f*S, -R2*S};
    float2 o[8];
#pragma unroll
    for (int r = 0; r < 8; r++) {
        float re = v[0].x, im = v[0].y;
#pragma unroll
        for (int j = 1; j < 8; j++) {
            const int k = (j*r) & 7;
            re += v[j].x*ct[k] - v[j].y*st[k];
            im += v[j].x*st[k] + v[j].y*ct[k];
        }
        o[r] = make_float2(re, im);
    }
#pragma unroll
    for (int r = 0; r < 8; r++) v[r] = o[r];
}

#define LSTR 390

// reg-in / reg-out FFT (caller synced; pa/pb per-line regions)
template<int SIGN>
__device__ __forceinline__ void fft384_rr(float2 vin[6], float2 vout[8],
                                          float2* pa, float2* pb,
                                          const float2* tw, int t) {
    dft6<SIGN>(vin);
#pragma unroll
    for (int r = 0; r < 6; r++) {
        float2 w = tw[t*r];
        if (SIGN > 0) w.y = -w.y;
        pb[6*t + r] = cmulf(vin[r], w);
    }
    __syncthreads();
    if (t < 48) {
        const int q = t % 6, p = t / 6;
        float2 v[8];
#pragma unroll
        for (int j = 0; j < 8; j++) v[j] = pb[q + 6*(p + 8*j)];
        dft8<SIGN>(v);
#pragma unroll
        for (int r = 0; r < 8; r++) {
            float2 w = tw[6*p*r];
            if (SIGN > 0) w.y = -w.y;
            pa[q + 6*(8*p + r)] = cmulf(v[r], w);
        }
    }
    __syncthreads();
    if (t < 48) {
#pragma unroll
        for (int j = 0; j < 8; j++) vout[j] = pa[t + 48*j];
        dft8<SIGN>(vout);
    }
}

// ---------------- twiddle init ----------------
__global__ void k_tw() {
    int i = threadIdx.x;
    if (i < 384) {
        float s, c;
        sincosf(-6.28318530717958647692f * (float)i / 384.f, &s, &c);
        g_tw[i] = make_float2(c, s);
    }
}

// ---------------- stats ----------------
__global__ void k_stats1(const float* __restrict__ x) {
    const int b = blockIdx.x >> 6, sl = blockIdx.x & 63;
    const float4* p = (const float4*)x + (size_t)b*589824 + (size_t)sl*9216;
    float s = 0.f, q = 0.f;
    for (int i = threadIdx.x; i < 9216; i += 256) {
        float4 v = p[i];
        s += v.x + v.y + v.z + v.w;
        q += v.x*v.x + v.y*v.y + v.z*v.z + v.w*v.w;
    }
    __shared__ float rs[256], rq[256];
    rs[threadIdx.x] = s; rq[threadIdx.x] = q;
    __syncthreads();
    for (int o = 128; o > 0; o >>= 1) {
        if (threadIdx.x < o) { rs[threadIdx.x] += rs[threadIdx.x+o]; rq[threadIdx.x] += rq[threadIdx.x+o]; }
        __syncthreads();
    }
    if (threadIdx.x == 0) g_part[blockIdx.x] = make_float2(rs[0], rq[0]);
}

__global__ void k_stats2() {
    __shared__ float2 sp[512];
    sp[threadIdx.x] = g_part[threadIdx.x];
    __syncthreads();
    if (threadIdx.x < 8) {
        float s = 0.f, q = 0.f;
        for (int i = 0; i < 64; i++) { float2 v = sp[threadIdx.x*64 + i]; s += v.x; q += v.y; }
        const float Nb = (float)(CC*HH*WW);
        float mean = s / Nb;
        float var = q / Nb - mean*mean;
        g_stats[threadIdx.x] = make_float2(mean, rsqrtf(var + 1e-5f));
    }
}

// ---------------- forward rows: UNPACKED (round-13 version) ----------------------
__global__ void k_fwd_u(const float* __restrict__ x) {
    __shared__ float2 sa[4*LSTR], sb[4*LSTR], tw[384];
    for (int i = threadIdx.x; i < 384; i += 256) tw[i] = g_tw[i];
    const int l = threadIdx.x & 3, t = threadIdx.x >> 2;
    const int line = blockIdx.x*4 + l;
    const int h = line % 384;
    const int c = (line / 384) & 15;
    const int b = line / (384*16);
    const float* xr = x + (((size_t)(b*CC + c)*HH + h) * WW);
    float2 vin[6], vout[8];
#pragma unroll
    for (int j = 0; j < 6; j++) vin[j] = make_float2(xr[t + 64*j], 0.f);
    __syncthreads();
    fft384_rr<-1>(vin, vout, sa + l*LSTR, sb + l*LSTR, tw, t);
    if (t < 48) {
        float2* dst = g_Xr + ((size_t)(b*CC + c)*WF)*HH + h;
#pragma unroll
        for (int r = 0; r < 8; r++) {
            const int n = t + 48*r;
            if (n < WF) dst[(size_t)n*HH] = vout[r];
        }
    }
}

// ---------------- forward column FFTs on g_Xr: warp-per-line lane mapping --------
// l = tid>>6 (4 lines), t = tid&63: a warp covers 32 consecutive t of ONE line ->
// 256B fully-coalesced gmem loads/stores. Instruction count identical.
__global__ void k_colf() {
    __shared__ float2 sa[4*LSTR], sb[4*LSTR], tw[384];
    for (int i = threadIdx.x; i < 384; i += 256) tw[i] = g_tw[i];
    const int l = threadIdx.x >> 6, t = threadIdx.x & 63;
    const size_t line = (size_t)blockIdx.x*4 + l;
    float2* g = g_Xr + line*HH;
    float2 vin[6], vout[8];
#pragma unroll
    for (int j = 0; j < 6; j++) vin[j] = g[t + 64*j];
    __syncthreads();
    fft384_rr<-1>(vin, vout, sa + l*LSTR, sb + l*LSTR, tw, t);
    if (t < 48) {
#pragma unroll
        for (int r = 0; r < 8; r++) g[t + 48*r] = vout[r];
    }
}

// ---------------- FUSED: (B@Xf)*T -> column IFFT -> C-GEMM -> Yf (round-8) -------
#define FZ_ZM    0                      // sZm: [32][386] float2 = 98816
#define FZ_UNI   98816                  // union: sX [16][384] f2 / pp 16 x 390 f2
#define FZ_CT    148736                 // sCt: [32][64] float2 = 16384
#define FZ_BT    165120                 // sBt: [16][32] float2 = 4096
#define FZ_TW    169216                 // tw: 384 float2 = 3072
#define FZ_PAR   172288                 // sPar: [32][8] float = 1024
#define FZ_TOTAL 173312

__global__ void __launch_bounds__(512, 1) k_fused(
    const float* __restrict__ B_re, const float* __restrict__ B_im,
    const float* __restrict__ C_re, const float* __restrict__ C_im,
    const float* __restrict__ theta, const float* __restrict__ alpha_raw,
    const float* __restrict__ beta,  const float* __restrict__ log_dc,
    const float* __restrict__ log_tau, const float* __restrict__ log_scale,
    const float* __restrict__ log_bw) {
    extern __shared__ char dynsm[];
    float2* sZm  = (float2*)(dynsm + FZ_ZM);
    float2* sX   = (float2*)(dynsm + FZ_UNI);
    float2* pp   = (float2*)(dynsm + FZ_UNI);
    float2* sCt  = (float2*)(dynsm + FZ_CT);
    float2* sBt  = (float2*)(dynsm + FZ_BT);
    float2* tw   = (float2*)(dynsm + FZ_TW);
    float*  sPar = (float*)(dynsm + FZ_PAR);

    const int tid = threadIdx.x;
    const int b = blockIdx.x / WF;
    const int w = blockIdx.x % WF;

    for (int i = tid; i < 384; i += 512) tw[i] = g_tw[i];
    for (int i = tid; i < CC*MM; i += 512) {
        const int c = i >> 5, m = i & 31;
        sBt[i] = make_float2(B_re[m*CC + c], B_im[m*CC + c]);
    }
    for (int i = tid; i < MM*KK; i += 512) {
        const int m = i >> 6, k = i & 63;
        sCt[i] = make_float2(C_re[k*MM + m], C_im[k*MM + m]);
    }
    if (tid < MM) {
        const int m = tid;
        float ar = alpha_raw[m];
        float spa = (ar > 20.f) ? ar : log1pf(expf(ar));
        float wc = expf(log_bw[m]);
        sPar[m*8+0] = spa;
        sPar[m*8+1] = beta[m];
        sPar[m*8+2] = expf(log_scale[m]);
        sPar[m*8+3] = expf(log_tau[m]);
        sPar[m*8+4] = expf(log_dc[m]);
        sPar[m*8+5] = 1.f / (wc*wc);
        sPar[m*8+6] = cosf(theta[m]);
        sPar[m*8+7] = sinf(theta[m]);
    }
    __syncthreads();

    // ---- T in registers ----
    const float TPN = 6.28318530717958647692f / 384.f;
    const float ox = (float)w * TPN;
    float2 Treg[24];
#pragma unroll
    for (int it = 0; it < 3; it++) {
        const int item = tid + 512*it;
        const int mq = item / 192, hp = item % 192;
#pragma unroll
        for (int mm = 0; mm < 4; mm++) {
            const int m = mq*4 + mm;
#pragma unroll
            for (int hh = 0; hh < 2; hh++) {
                const int h = 2*hp + hh;
                const float oy = (float)((h < 192) ? h : h - 384) * TPN;
                const float vd = sPar[m*8+6]*ox + sPar[m*8+7]*oy;
                const float w2 = ox*ox + oy*oy;
                const float wp2 = w2 - vd*vd;
                float Dre = sPar[m*8+0] + sPar[m*8+3]*wp2;
                float Dim = sPar[m*8+2]*vd - sPar[m*8+1];
                const float qq = w2 * sPar[m*8+5];
                const float q2 = qq*qq;
                const float bt = 1.f + q2*q2;
                Dre *= bt; Dim *= bt;
                const float inv = sPar[m*8+4] / (Dre*Dre + Dim*Dim);
                Treg[it*8 + mm*2 + hh] = make_float2(Dre*inv, -Dim*inv);
            }
        }
    }

    const float HWf = (float)(HH*WW);
    const float2 st = g_stats[b];
    const float mean = st.x, rstd = st.y;

    // ---- load Xf tile (normalized); DC fix for all channels ----
    {
        const float4* src = (const float4*)(g_Xr + ((size_t)(b*CC)*WF + w)*HH);
#pragma unroll
        for (int itr = 0; itr < 6; itr++) {
            const int idx = tid + 512*itr;
            const int c = idx / 192, q = idx % 192;
            float4 v = *(const float4*)((const char*)src + ((size_t)c*WF*HH + 2*q)*8);
            if (w == 0 && q == 0) v.x -= mean * HWf;
            v.x *= rstd; v.y *= rstd; v.z *= rstd; v.w *= rstd;
            *(float4*)(sX + c*384 + 2*q) = v;
        }
    }
    __syncthreads();

    // ---- GEMM1 + T: Zspec[m][h] ----
#pragma unroll
    for (int it = 0; it < 3; it++) {
        const int item = tid + 512*it;
        const int mq = item / 192, hp = item % 192;
        float2 acc[4][2];
#pragma unroll
        for (int mm = 0; mm < 4; mm++) { acc[mm][0] = make_float2(0.f,0.f); acc[mm][1] = make_float2(0.f,0.f); }
#pragma unroll
        for (int c = 0; c < CC; c++) {
            const float4 xv = *(const float4*)(sX + c*384 + 2*hp);
            const float2 x0 = make_float2(xv.x, xv.y);
            const float2 x1 = make_float2(xv.z, xv.w);
            const float4 ba = *(const float4*)(sBt + c*32 + mq*4);
            const float4 bb = *(const float4*)(sBt + c*32 + mq*4 + 2);
            const float2 b0 = make_float2(ba.x, ba.y);
            const float2 b1 = make_float2(ba.z, ba.w);
            const float2 b2 = make_float2(bb.x, bb.y);
            const float2 b3 = make_float2(bb.z, bb.w);
            cfma(acc[0][0], b0, x0); cfma(acc[0][1], b0, x1);
            cfma(acc[1][0], b1, x0); cfma(acc[1][1], b1, x1);
            cfma(acc[2][0], b2, x0); cfma(acc[2][1], b2, x1);
            cfma(acc[3][0], b3, x0); cfma(acc[3][1], b3, x1);
        }
#pragma unroll
        for (int mm = 0; mm < 4; mm++) {
            const float2 z0 = cmulf(acc[mm][0], Treg[it*8 + mm*2 + 0]);
            const float2 z1 = cmulf(acc[mm][1], Treg[it*8 + mm*2 + 1]);
            *(float4*)(sZm + (mq*4 + mm)*386 + 2*hp) = make_float4(z0.x, z0.y, z1.x, z1.y);
        }
    }
    __syncthreads();

    // ---- column IFFT of 32 rows (4 groups of 8 lines) ----
    {
        const int l = tid & 7, t = tid >> 3;
        float2* pa = pp + l*LSTR;
        float2* pb = pp + 8*LSTR + l*LSTR;
#pragma unroll 1
        for (int g = 0; g < 4; g++) {
            float2* zrow = sZm + (g*8 + l)*386;
            float2 vin[6], vout[8];
#pragma unroll
            for (int j = 0; j < 6; j++) vin[j] = zrow[t + 64*j];
            fft384_rr<1>(vin, vout, pa, pb, tw, t);
            if (t < 48) {
#pragma unroll
                for (int r = 0; r < 8; r++) zrow[t + 48*r] = vout[r];
            }
            __syncthreads();
        }
    }

    // ---- GEMM2 (4k x 2h): Yf[k][h] = sum_m C[k][m] * Z[m][h] ----
#pragma unroll 1
    for (int it = 0; it < 6; it++) {
        const int item = tid + 512*it;
        const int kq = item / 192, hp = item % 192;
        float2 a00 = make_float2(0.f,0.f), a01 = a00, a10 = a00, a11 = a00;
        float2 a20 = a00, a21 = a00, a30 = a00, a31 = a00;
#pragma unroll
        for (int m = 0; m < MM; m++) {
            const float4 zz = *(const float4*)(sZm + m*386 + 2*hp);
            const float2 z0 = make_float2(zz.x, zz.y);
            const float2 z1 = make_float2(zz.z, zz.w);
            const float4 ca = *(const float4*)(sCt + m*64 + kq*4);
            const float4 cb = *(const float4*)(sCt + m*64 + kq*4 + 2);
            const float2 c0 = make_float2(ca.x, ca.y);
            const float2 c1 = make_float2(ca.z, ca.w);
            const float2 c2 = make_float2(cb.x, cb.y);
            const float2 c3 = make_float2(cb.z, cb.w);
            cfma(a00, c0, z0); cfma(a01, c0, z1);
            cfma(a10, c1, z0); cfma(a11, c1, z1);
            cfma(a20, c2, z0); cfma(a21, c2, z1);
            cfma(a30, c3, z0); cfma(a31, c3, z1);
        }
        const size_t base = ((size_t)(b*KK + kq*4)*WF + w)*HH + 2*hp;
        *(float4*)(g_Yf + base)                    = make_float4(a00.x, a00.y, a01.x, a01.y);
        *(float4*)(g_Yf + base + (size_t)WF*HH)    = make_float4(a10.x, a10.y, a11.x, a11.y);
        *(float4*)(g_Yf + base + (size_t)2*WF*HH)  = make_float4(a20.x, a20.y, a21.x, a21.y);
        *(float4*)(g_Yf + base + (size_t)3*WF*HH)  = make_float4(a30.x, a30.y, a31.x, a31.y);
    }
}

// ---------------- inverse rows: 8 lines/block, 512 threads (round-13 version) ---
__global__ void __launch_bounds__(512) k_inv_p(float* __restrict__ y) {
    __shared__ float2 sa[8*LSTR], sb[8*LSTR], tw[384];
    const int tid = threadIdx.x;
    for (int i = tid; i < 384; i += 512) tw[i] = g_tw[i];
    const int l = tid & 7, t = tid >> 3;
    const int line0 = blockIdx.x * 8;
    const int h0 = line0 % 384;
    const int kp = (line0 / 384) & 31;
    const int b  = line0 / (384*32);
    const int h = h0 + l;
    const size_t base1 = ((size_t)(b*KK + 2*kp)*WF)*HH + h;
    const size_t base2 = base1 + (size_t)WF*HH;

    float2 vin[6];
#pragma unroll
    for (int i = 0; i < 6; i++) {
        const int w = t + 64*i;
        const int wi = (w < WF) ? w : (384 - w);
        const float2 q1 = g_Yf[base1 + (size_t)wi*HH];
        const float2 q2 = g_Yf[base2 + (size_t)wi*HH];
        float2 z;
        if (w == 0 || w == 192) {
            z = make_float2(q1.x, q2.x);
        } else if (w < WF) {
            z = make_float2(q1.x - q2.y, q1.y + q2.x);
        } else {
            z = make_float2(q1.x + q2.y, q2.x - q1.y);
        }
        vin[i] = z;
    }
    __syncthreads();     // tw staged

    float2* pa = sa + l*LSTR;
    float2* pb = sb + l*LSTR;
    dft6<1>(vin);
#pragma unroll
    for (int r = 0; r < 6; r++) {
        float2 wv = tw[t*r]; wv.y = -wv.y;
        pb[6*t + r] = cmulf(vin[r], wv);
    }
    __syncthreads();
    if (t < 48) {
        const int q = t % 6, p = t / 6;
        float2 v[8];
#pragma unroll
        for (int j = 0; j < 8; j++) v[j] = pb[q + 6*(p + 8*j)];
        dft8<1>(v);
#pragma unroll
        for (int r = 0; r < 8; r++) {
            float2 wv = tw[6*p*r]; wv.y = -wv.y;
            pa[q + 6*(8*p + r)] = cmulf(v[r], wv);
        }
    }
    __syncthreads();
    if (t < 48) {
        float2 v[8];
#pragma unroll
        for (int j = 0; j < 8; j++) v[j] = pa[t + 48*j];
        dft8<1>(v);
#pragma unroll
        for (int r = 0; r < 8; r++) pb[t + 48*r] = v[r];
    }
    __syncthreads();

    const float sc = 1.f / (float)(HH*WW);
    float* y0 = y + ((size_t)(b*KK + 2*kp)*HH + h0) * WW;
    float* y1 = y0 + (size_t)HH*WW;
#pragma unroll
    for (int i = 0; i < 6; i++) {
        const int idx = tid + 512*i;
        const int rh = idx / 384;
        const int n  = idx % 384;
        const float2 v = sb[rh*LSTR + n];
        y0[(size_t)rh*WW + n] = v.x * sc;
        y1[(size_t)rh*WW + n] = v.y * sc;
    }
}

// ---------------- launch ----------------
extern "C" void kernel_launch(void* const* d_in, const int* in_sizes, int n_in,
                              void* d_out, int out_size) {
    const float* x         = (const float*)d_in[0];
    const float* theta     = (const float*)d_in[1];
    const float* B_re      = (const float*)d_in[2];
    const float* B_im      = (const float*)d_in[3];
    const float* C_re      = (const float*)d_in[4];
    const float* C_im      = (const float*)d_in[5];
    const float* alpha_raw = (const float*)d_in[6];
    const float* beta      = (const float*)d_in[7];
    const float* log_dc    = (const float*)d_in[8];
    const float* log_tau   = (const float*)d_in[9];
    const float* log_scale = (const float*)d_in[10];
    const float* log_bw    = (const float*)d_in[11];
    float* y = (float*)d_out;

    cudaFuncSetAttribute(k_fused, cudaFuncAttributeMaxDynamicSharedMemorySize, FZ_TOTAL);

    k_tw<<<1, 384>>>();
    k_stats1<<<512, 256>>>(x);
    k_stats2<<<1, 512>>>();
    k_fwd_u<<<(BB*CC*HH)/4, 256>>>(x);                  // 12288 blocks
    k_colf<<<(BB*CC*WF)/4, 256>>>();                    // 6176 blocks
    k_fused<<<BB*WF, 512, FZ_TOTAL>>>(B_re, B_im, C_re, C_im, theta, alpha_raw,
                                      beta, log_dc, log_tau, log_scale, log_bw);
    k_inv_p<<<(BB*MM*HH)/8, 512>>>(y);                  // 12288 blocks
}